// round 2
// baseline (speedup 1.0000x reference)
#include <cuda_runtime.h>
#include <math.h>

#define B_  4
#define S_  4096
#define D_  64
#define BQ  128
#define BK  128
#define QT_PER_B   32          /* S/BQ */
#define UNITS_PER_B 528        /* 32*33/2 */
#define NUNITS     2112        /* 4 * 528 */

/* strides (floats) with padding */
#define QT_STRIDE (BQ + 4)     /* 132 */
#define KT_STRIDE (BK + 4)     /* 132 */
#define VS_STRIDE (D_ + 4)     /* 68  */
#define ET_STRIDE (BQ + 4)     /* 132 */

#define SMEM_FLOATS (64*QT_STRIDE + 64*KT_STRIDE + BK*VS_STRIDE + BK*ET_STRIDE)
#define SMEM_BYTES  (SMEM_FLOATS * 4)

/* scratch: partial row sums and partial O per (b, qt, kt) unit */
__device__ float g_Lp[(size_t)NUNITS * 128];
__device__ float g_Op[(size_t)NUNITS * 128 * 64];
__device__ float g_invL[B_ * S_];

__device__ __forceinline__ float fast_exp(float x) {
    /* exp(x) = 2^(x*log2e); valid for |x| < ~80. FFMA-only (no MUFU). */
    float t = x * 1.4426950408889634f;
    float r = t + 12582912.0f;                 /* round-to-nearest-even */
    int   n = __float_as_int(r) - 0x4B400000;  /* integer part */
    float f = t - (r - 12582912.0f);           /* frac in [-0.5, 0.5] */
    float p = 1.3333558e-3f;
    p = fmaf(p, f, 9.6181291e-3f);
    p = fmaf(p, f, 5.5504109e-2f);
    p = fmaf(p, f, 2.4022651e-1f);
    p = fmaf(p, f, 6.9314718e-1f);
    p = fmaf(p, f, 1.0f);
    return __int_as_float(__float_as_int(p) + (n << 23));
}

/* ------------------------------------------------------------------ */
/* Kernel A: one (q-tile, k-tile) 128x128 unit per block.             */
/* Computes E = exp(QK^T/8) with causal mask, writes E (unnormalized) */
/* into the weights output region, partial row sums to g_Lp, and the  */
/* partial O = E@V tile to g_Op.                                      */
/* ------------------------------------------------------------------ */
__global__ void __launch_bounds__(256, 1)
attn_tiles(const float* __restrict__ Q, const float* __restrict__ K,
           const float* __restrict__ V, float* __restrict__ outW,
           int writeW)
{
    extern __shared__ float sm[];
    float* Qt = sm;                          /* [64][132]  Qt[d][i]  */
    float* Kt = Qt + 64 * QT_STRIDE;         /* [64][132]  Kt[d][k]  */
    float* Vs = Kt + 64 * KT_STRIDE;         /* [128][68]  Vs[k][d]  */
    float* Et = Vs + BK * VS_STRIDE;         /* [128][132] Et[j][i]  */

    const int b = blockIdx.y;
    const int x = blockIdx.x;
    int qt = (int)((sqrtf(8.0f * (float)x + 1.0f) - 1.0f) * 0.5f);
    while ((qt + 1) * (qt + 2) / 2 <= x) qt++;
    while (qt * (qt + 1) / 2 > x) qt--;
    const int kt   = x - qt * (qt + 1) / 2;
    const int unit = b * UNITS_PER_B + x;

    const int tx  = threadIdx.x;   /* 0..15 */
    const int ty  = threadIdx.y;   /* 0..15 */
    const int tid = ty * 16 + tx;

    const float* Qb = Q + ((size_t)b * S_ + (size_t)qt * BQ) * D_;
    const float* Kb = K + ((size_t)b * S_ + (size_t)kt * BK) * D_;
    const float* Vb = V + ((size_t)b * S_ + (size_t)kt * BK) * D_;

    /* fill shared tiles (Q,K transposed to [d][row]; V natural) */
    for (int e = tid; e < BQ * D_; e += 256) {
        int i = e >> 6, d = e & 63;
        Qt[d * QT_STRIDE + i] = Qb[e];
        Kt[d * KT_STRIDE + i] = Kb[e];
        Vs[i * VS_STRIDE + d] = Vb[e];
    }
    __syncthreads();

    /* ---- S = Q K^T over the 128x128 tile; 8x8 per thread as 2x2 of 4x4 ---- */
    float acc[2][2][4][4];
#pragma unroll
    for (int a0 = 0; a0 < 2; a0++)
#pragma unroll
        for (int a1 = 0; a1 < 2; a1++)
#pragma unroll
            for (int a2 = 0; a2 < 4; a2++)
#pragma unroll
                for (int a3 = 0; a3 < 4; a3++) acc[a0][a1][a2][a3] = 0.0f;

#pragma unroll 4
    for (int d = 0; d < 64; d++) {
        const float* qrow = Qt + d * QT_STRIDE;
        const float* krow = Kt + d * KT_STRIDE;
        float4 q0 = *(const float4*)(qrow + 4 * ty);
        float4 q1 = *(const float4*)(qrow + 64 + 4 * ty);
        float4 k0 = *(const float4*)(krow + 4 * tx);
        float4 k1 = *(const float4*)(krow + 64 + 4 * tx);
        float qv[2][4] = {{q0.x, q0.y, q0.z, q0.w}, {q1.x, q1.y, q1.z, q1.w}};
        float kv[2][4] = {{k0.x, k0.y, k0.z, k0.w}, {k1.x, k1.y, k1.z, k1.w}};
#pragma unroll
        for (int rr = 0; rr < 2; rr++)
#pragma unroll
            for (int cc = 0; cc < 2; cc++)
#pragma unroll
                for (int r = 0; r < 4; r++)
#pragma unroll
                    for (int c = 0; c < 4; c++)
                        acc[rr][cc][r][c] = fmaf(qv[rr][r], kv[cc][c], acc[rr][cc][r][c]);
    }

    /* ---- mask + exp (in place) + row sums ---- */
    const bool diag = (qt == kt);
    float rsum[2][4];
#pragma unroll
    for (int rr = 0; rr < 2; rr++)
#pragma unroll
        for (int r = 0; r < 4; r++) rsum[rr][r] = 0.0f;

#pragma unroll
    for (int rr = 0; rr < 2; rr++) {
#pragma unroll
        for (int r = 0; r < 4; r++) {
            const int i = rr * 64 + 4 * ty + r;
#pragma unroll
            for (int cc = 0; cc < 2; cc++) {
#pragma unroll
                for (int c = 0; c < 4; c++) {
                    const int j = cc * 64 + 4 * tx + c;
                    float s = acc[rr][cc][r][c] * 0.125f;
                    float e = (diag && (j > i)) ? 0.0f : fast_exp(s);
                    acc[rr][cc][r][c] = e;
                    rsum[rr][r] += e;
                }
            }
        }
    }

    /* reduce row sums across tx (lanes: bit0..3 == tx) */
#pragma unroll
    for (int rr = 0; rr < 2; rr++)
#pragma unroll
        for (int r = 0; r < 4; r++) {
            float v = rsum[rr][r];
            v += __shfl_xor_sync(0xffffffffu, v, 1);
            v += __shfl_xor_sync(0xffffffffu, v, 2);
            v += __shfl_xor_sync(0xffffffffu, v, 4);
            v += __shfl_xor_sync(0xffffffffu, v, 8);
            rsum[rr][r] = v;
        }
    if (tx == 0) {
#pragma unroll
        for (int rr = 0; rr < 2; rr++)
#pragma unroll
            for (int r = 0; r < 4; r++)
                g_Lp[(size_t)unit * 128 + rr * 64 + 4 * ty + r] = rsum[rr][r];
    }

    /* ---- write unnormalized E to global weights + transposed to smem ---- */
#pragma unroll
    for (int rr = 0; rr < 2; rr++) {
#pragma unroll
        for (int r = 0; r < 4; r++) {
            const int i = rr * 64 + 4 * ty + r;
            float* grow = outW + ((size_t)(b * S_ + qt * BQ + i)) * S_ + (size_t)kt * BK;
#pragma unroll
            for (int cc = 0; cc < 2; cc++) {
                if (writeW) {
                    float4 w;
                    w.x = acc[rr][cc][r][0]; w.y = acc[rr][cc][r][1];
                    w.z = acc[rr][cc][r][2]; w.w = acc[rr][cc][r][3];
                    *(float4*)(grow + cc * 64 + 4 * tx) = w;
                }
#pragma unroll
                for (int c = 0; c < 4; c++)
                    Et[(cc * 64 + 4 * tx + c) * ET_STRIDE + i] = acc[rr][cc][r][c];
            }
        }
    }
    __syncthreads();

    /* ---- partial O = E @ V  (rows {4ty..}{64+4ty..}, cols 4tx..4tx+3) ---- */
    float o[2][4][4];
#pragma unroll
    for (int rr = 0; rr < 2; rr++)
#pragma unroll
        for (int r = 0; r < 4; r++)
#pragma unroll
            for (int c = 0; c < 4; c++) o[rr][r][c] = 0.0f;

#pragma unroll 4
    for (int j = 0; j < BK; j++) {
        const float* erow = Et + j * ET_STRIDE;
        float4 e0 = *(const float4*)(erow + 4 * ty);
        float4 e1 = *(const float4*)(erow + 64 + 4 * ty);
        float4 vv = *(const float4*)(Vs + j * VS_STRIDE + 4 * tx);
        float ev[2][4] = {{e0.x, e0.y, e0.z, e0.w}, {e1.x, e1.y, e1.z, e1.w}};
        float vf[4] = {vv.x, vv.y, vv.z, vv.w};
#pragma unroll
        for (int rr = 0; rr < 2; rr++)
#pragma unroll
            for (int r = 0; r < 4; r++)
#pragma unroll
                for (int c = 0; c < 4; c++)
                    o[rr][r][c] = fmaf(ev[rr][r], vf[c], o[rr][r][c]);
    }

    float* Ob = g_Op + (size_t)unit * (128 * 64);
#pragma unroll
    for (int rr = 0; rr < 2; rr++)
#pragma unroll
        for (int r = 0; r < 4; r++) {
            const int i = rr * 64 + 4 * ty + r;
            float4 w;
            w.x = o[rr][r][0]; w.y = o[rr][r][1]; w.z = o[rr][r][2]; w.w = o[rr][r][3];
            *(float4*)(Ob + i * 64 + 4 * tx) = w;
        }
}

/* ---------------- Kernel B1: invL per row ---------------- */
__global__ void __launch_bounds__(256)
reduce_l()
{
    int t = blockIdx.x * 256 + threadIdx.x;       /* 0..16383 */
    if (t >= B_ * S_) return;
    int b = t >> 12, q = t & (S_ - 1);
    int qt = q >> 7, i = q & 127;
    int tri = qt * (qt + 1) / 2;
    float s = 0.0f;
    for (int kt = 0; kt <= qt; kt++)
        s += g_Lp[((size_t)(b * UNITS_PER_B + tri + kt)) * 128 + i];
    g_invL[t] = 1.0f / s;
}

/* ---------------- Kernel B2: O = (sum of partials) * invL ---------------- */
__global__ void __launch_bounds__(256)
reduce_o(float* __restrict__ outV)
{
    int t = blockIdx.x * 256 + threadIdx.x;       /* per (b,q,d4): 262144 */
    if (t >= B_ * S_ * (D_ / 4)) return;
    int d4 = t & 15;
    int q  = (t >> 4) & (S_ - 1);
    int b  = t >> 16;
    int qt = q >> 7, i = q & 127;
    int tri = qt * (qt + 1) / 2;
    float ax = 0.f, ay = 0.f, az = 0.f, aw = 0.f;
    for (int kt = 0; kt <= qt; kt++) {
        const float4 v = *(const float4*)(g_Op +
            ((size_t)(b * UNITS_PER_B + tri + kt) * 128 + i) * 64 + d4 * 4);
        ax += v.x; ay += v.y; az += v.z; aw += v.w;
    }
    float inv = g_invL[b * S_ + q];
    float4 r; r.x = ax * inv; r.y = ay * inv; r.z = az * inv; r.w = aw * inv;
    *(float4*)(outV + ((size_t)(b * S_ + q)) * D_ + d4 * 4) = r;
}

/* ---------------- Kernel C: normalize weights + zero upper tiles -------- */
__global__ void __launch_bounds__(256)
norm_w(float* __restrict__ outW)
{
    size_t t = (size_t)blockIdx.x * 256 + threadIdx.x;   /* float4 index */
    /* total float4s = 4*4096*1024 = 16,777,216 */
    int kq = (int)(t & 1023);                 /* float4 col index */
    int q  = (int)((t >> 10) & (S_ - 1));
    int b  = (int)(t >> 22);
    float4* p = (float4*)outW + t;
    int k = kq * 4;
    if ((k >> 7) > (q >> 7)) {
        float4 z; z.x = z.y = z.z = z.w = 0.0f;
        *p = z;
    } else {
        float inv = g_invL[b * S_ + q];
        float4 v = *p;
        v.x *= inv; v.y *= inv; v.z *= inv; v.w *= inv;
        *p = v;
    }
}

/* ------------------------------------------------------------------ */
extern "C" void kernel_launch(void* const* d_in, const int* in_sizes, int n_in,
                              void* d_out, int out_size)
{
    const float* Q = (const float*)d_in[0];
    const float* K = (const float*)d_in[1];
    const float* V = (const float*)d_in[2];

    const long long VE = (long long)B_ * S_ * D_;       /* 1,048,576  */
    const long long WE = (long long)B_ * S_ * S_;       /* 67,108,864 */

    float* outVec = nullptr;
    float* outW   = nullptr;
    int writeW = 0;
    if ((long long)out_size == VE + WE) {
        outVec = (float*)d_out;
        outW   = (float*)d_out + VE;
        writeW = 1;
    } else if ((long long)out_size == WE) {
        outW   = (float*)d_out;
        writeW = 1;
    } else {
        outVec = (float*)d_out;
    }
    float* wPtr = writeW ? outW : (float*)d_out;  /* never dereferenced when !writeW */

    cudaFuncSetAttribute(attn_tiles, cudaFuncAttributeMaxDynamicSharedMemorySize,
                         SMEM_BYTES);

    dim3 gA(UNITS_PER_B, B_);
    dim3 bA(16, 16);
    attn_tiles<<<gA, bA, SMEM_BYTES>>>(Q, K, V, wPtr, writeW);

    reduce_l<<<(B_ * S_ + 255) / 256, 256>>>();

    if (outVec)
        reduce_o<<<(B_ * S_ * (D_ / 4) + 255) / 256, 256>>>(outVec);

    if (writeW) {
        long long nf4 = WE / 4;                 /* 16,777,216 */
        norm_w<<<(unsigned)(nf4 / 256), 256>>>(outW);
    }
}